// round 6
// baseline (speedup 1.0000x reference)
#include <cuda_runtime.h>
#include <cuda_bf16.h>
#include <cstdint>

// Problem constants (fixed by the dataset)
#define N_NODES 100000
#define N_EDGES 1250000
#define IN_CH   128
#define OUT_CH  64

// Scratch (no cudaMalloc allowed)
__device__ __align__(16) float g_h[(size_t)N_NODES * OUT_CH];   // 25.6 MB
__device__ float g_dis[N_NODES];            // deg, then deg^-1/2
__device__ int   g_is64;                    // 1 if edge_index stored as int64

// ---------------------------------------------------------------------------
// Edge-index access through an int32 view, layout-agnostic.
//  int32 layout: w[e] (row block), w[N_EDGES+e] (col block)
//  int64 LE layout: low word at w[2*e] / w[2*(N_EDGES+e)] (values < 2^31)
// ---------------------------------------------------------------------------
__device__ __forceinline__ int edge_row(const int* __restrict__ w, int e, int is64) {
    return is64 ? w[2 * e] : w[e];
}
__device__ __forceinline__ int edge_col(const int* __restrict__ w, int e, int is64) {
    return is64 ? w[2 * (N_EDGES + e)] : w[N_EDGES + e];
}

// ---------------------------------------------------------------------------
// 0) dtype detector: if the odd 32-bit words (high halves under an int64
//    interpretation) are all zero across 1024 samples, it's int64 storage.
//    Under int32 storage those words are uniform in [0,100000) — P(all 0)≈0.
// ---------------------------------------------------------------------------
__global__ void k_detect(const int* __restrict__ w) {
    __shared__ int nz;
    if (threadIdx.x == 0) nz = 0;
    __syncthreads();
    int bad = 0;
    #pragma unroll
    for (int i = 0; i < 4; i++) {
        int idx = 2 * (threadIdx.x + i * 256) + 1;   // odd words, first 2048 words
        if (w[idx] != 0) bad = 1;
    }
    if (bad) atomicOr(&nz, 1);
    __syncthreads();
    if (threadIdx.x == 0) g_is64 = (nz == 0) ? 1 : 0;
}

// ---------------------------------------------------------------------------
// f32x2 packed-FMA helpers (sm_100+; ptxas emits FFMA2). Compute-only asm.
// ---------------------------------------------------------------------------
__device__ __forceinline__ void fma2(unsigned long long& acc,
                                     unsigned long long a,
                                     unsigned long long b) {
    asm("fma.rn.f32x2 %0, %1, %2, %0;" : "+l"(acc) : "l"(a), "l"(b));
}
__device__ __forceinline__ unsigned long long pack2(float lo, float hi) {
    unsigned long long r;
    asm("mov.b64 %0, {%1, %2};" : "=l"(r) : "f"(lo), "f"(hi));
    return r;
}
__device__ __forceinline__ float2 unpack2(unsigned long long v) {
    float2 f;
    asm("mov.b64 {%0, %1}, %2;" : "=f"(f.x), "=f"(f.y) : "l"(v));
    return f;
}

// ---------------------------------------------------------------------------
// 1) zero degree buffer
// ---------------------------------------------------------------------------
__global__ void k_zero_deg() {
    int i = blockIdx.x * blockDim.x + threadIdx.x;
    if (i < N_NODES) g_dis[i] = 0.0f;
}

// ---------------------------------------------------------------------------
// 2) weighted in-degree: deg[row] += w[e]
// ---------------------------------------------------------------------------
__global__ void k_deg_accum(const int* __restrict__ ei,
                            const float* __restrict__ ew) {
    int e = blockIdx.x * blockDim.x + threadIdx.x;
    if (e < N_EDGES) {
        int is64 = g_is64;
        int r = edge_row(ei, e, is64);
        if ((unsigned)r < N_NODES)
            atomicAdd(&g_dis[r], ew[e]);
    }
}

// ---------------------------------------------------------------------------
// 3) deg -> deg^-1/2 (0 where deg == 0)
// ---------------------------------------------------------------------------
__global__ void k_deg_inv_sqrt() {
    int i = blockIdx.x * blockDim.x + threadIdx.x;
    if (i < N_NODES) {
        float d = g_dis[i];
        g_dis[i] = (d > 0.0f) ? rsqrtf(d) : 0.0f;
    }
}

// ---------------------------------------------------------------------------
// 4) GEMM: g_h[100000,64] = x[100000,128] @ W[128,64]
//    256 threads, tile 64 nodes x 64 out, thread 4x4, FFMA2 accumulation.
// ---------------------------------------------------------------------------
#define XS_STRIDE 68   // 64 + 4 pad floats: float4-aligned, bank-shifted rows

__global__ void __launch_bounds__(256) k_gemm(const float* __restrict__ x,
                                              const float* __restrict__ W) {
    __shared__ __align__(16) float Ws[IN_CH * OUT_CH];   // 32 KB
    __shared__ __align__(16) float Xs[64 * XS_STRIDE];   // 17 KB

    const int t  = threadIdx.x;
    const int tx = t & 15;        // out cols tx*4 .. tx*4+3
    const int ty = t >> 4;        // nodes ty*4 .. ty*4+3
    const int nb = blockIdx.x * 64;

    {
        const float4* W4 = reinterpret_cast<const float4*>(W);
        float4* Ws4 = reinterpret_cast<float4*>(Ws);
        #pragma unroll
        for (int i = 0; i < (IN_CH * OUT_CH / 4) / 256; i++)
            Ws4[t + i * 256] = W4[t + i * 256];
    }

    unsigned long long acc[4][2];
    #pragma unroll
    for (int i = 0; i < 4; i++) { acc[i][0] = 0ull; acc[i][1] = 0ull; }

    #pragma unroll
    for (int kc = 0; kc < 2; kc++) {
        {
            const float4* x4 = reinterpret_cast<const float4*>(x);
            #pragma unroll
            for (int i = 0; i < 4; i++) {
                int f = t + i * 256;           // 0..1023
                int node = f >> 4;
                int kk4  = f & 15;
                int gn = nb + node;
                float4 v = make_float4(0.f, 0.f, 0.f, 0.f);
                if (gn < N_NODES)
                    v = x4[(size_t)gn * (IN_CH / 4) + kc * 16 + kk4];
                *reinterpret_cast<float4*>(&Xs[node * XS_STRIDE + kk4 * 4]) = v;
            }
        }
        __syncthreads();

        #pragma unroll 8
        for (int kk = 0; kk < 64; kk++) {
            float4 w = *reinterpret_cast<const float4*>(
                &Ws[(kc * 64 + kk) * OUT_CH + tx * 4]);
            unsigned long long wA = pack2(w.x, w.y);
            unsigned long long wB = pack2(w.z, w.w);
            #pragma unroll
            for (int i = 0; i < 4; i++) {
                float xv = Xs[(ty * 4 + i) * XS_STRIDE + kk];
                unsigned long long x2 = pack2(xv, xv);
                fma2(acc[i][0], x2, wA);
                fma2(acc[i][1], x2, wB);
            }
        }
        __syncthreads();
    }

    #pragma unroll
    for (int i = 0; i < 4; i++) {
        int node = nb + ty * 4 + i;
        if (node < N_NODES) {
            float2 a = unpack2(acc[i][0]);
            float2 b = unpack2(acc[i][1]);
            float4 v = make_float4(a.x, a.y, b.x, b.y);
            *reinterpret_cast<float4*>(&g_h[(size_t)node * OUT_CH + tx * 4]) = v;
        }
    }
}

// ---------------------------------------------------------------------------
// 5) out = bias broadcast (d_out is poisoned; fully overwrite)
// ---------------------------------------------------------------------------
__global__ void k_init_out(const float* __restrict__ b, float* __restrict__ out) {
    int i = blockIdx.x * blockDim.x + threadIdx.x;   // float4 index
    if (i < N_NODES * (OUT_CH / 4)) {
        const float4* b4 = reinterpret_cast<const float4*>(b);
        reinterpret_cast<float4*>(out)[i] = b4[i & (OUT_CH / 4 - 1)];
    }
}

// ---------------------------------------------------------------------------
// 6) scatter: out[row] += h[col] * dis[row]*dis[col]
//    16 threads per edge, one float4 vector atomic per thread.
// ---------------------------------------------------------------------------
__global__ void __launch_bounds__(256) k_scatter(const int* __restrict__ ei,
                                                 float* __restrict__ out) {
    long long gt = (long long)blockIdx.x * blockDim.x + threadIdx.x;
    int e = (int)(gt >> 4);
    int c = (int)(gt & 15);
    if (e >= N_EDGES) return;

    int is64 = g_is64;
    int r   = edge_row(ei, e, is64);   // destination
    int col = edge_col(ei, e, is64);   // source
    if ((unsigned)r >= N_NODES || (unsigned)col >= N_NODES) return;

    float norm = g_dis[r] * g_dis[col];
    if (norm == 0.0f) return;

    float4 hv = *reinterpret_cast<const float4*>(&g_h[(size_t)col * OUT_CH + c * 4]);
    float4 v  = make_float4(hv.x * norm, hv.y * norm, hv.z * norm, hv.w * norm);

    float4* p = reinterpret_cast<float4*>(out + (size_t)r * OUT_CH + c * 4);
#if __CUDA_ARCH__ >= 900
    atomicAdd(p, v);          // 16B-aligned vector RED
#else
    float* ps = reinterpret_cast<float*>(p);
    atomicAdd(ps + 0, v.x);
    atomicAdd(ps + 1, v.y);
    atomicAdd(ps + 2, v.z);
    atomicAdd(ps + 3, v.w);
#endif
}

// ---------------------------------------------------------------------------
// launch
// ---------------------------------------------------------------------------
extern "C" void kernel_launch(void* const* d_in, const int* in_sizes, int n_in,
                              void* d_out, int out_size) {
    const float* x  = (const float*)d_in[0];
    const int*   ei = (const int*)d_in[1];     // int32 view; layout detected on-device
    const float* ew = (const float*)d_in[2];
    const float* W  = (const float*)d_in[3];
    const float* b  = (const float*)d_in[4];
    float* out = (float*)d_out;

    // dtype layout detection (1 block, trivial cost)
    k_detect<<<1, 256>>>(ei);

    // degree pipeline
    k_zero_deg<<<(N_NODES + 255) / 256, 256>>>();
    k_deg_accum<<<(N_EDGES + 255) / 256, 256>>>(ei, ew);
    k_deg_inv_sqrt<<<(N_NODES + 255) / 256, 256>>>();

    // dense transform
    k_gemm<<<(N_NODES + 63) / 64, 256>>>(x, W);

    // bias init + scatter
    k_init_out<<<(N_NODES * (OUT_CH / 4) + 255) / 256, 256>>>(b, out);
    long long scatter_threads = (long long)N_EDGES * 16;
    k_scatter<<<(unsigned)((scatter_threads + 255) / 256), 256>>>(ei, out);
}

// round 7
// speedup vs baseline: 1.1339x; 1.1339x over previous
#include <cuda_runtime.h>
#include <cuda_bf16.h>
#include <cstdint>

// Problem constants (fixed by the dataset)
#define N_NODES 100000
#define N_EDGES 1250000
#define IN_CH   128
#define OUT_CH  64

#define SCAN_BLK   1024
#define N_SCAN_BLK ((N_NODES + SCAN_BLK - 1) / SCAN_BLK)   // 98

// Scratch (no cudaMalloc allowed)
__device__ __align__(16) float g_h[(size_t)N_NODES * OUT_CH];   // 25.6 MB
__device__ float g_dis[N_NODES];            // deg, then deg^-1/2
__device__ int   g_cnt[N_NODES];            // in-degree (edge count)
__device__ int   g_off[N_NODES];            // excl. prefix -> end cursor after fill
__device__ int   g_bsum[N_SCAN_BLK];        // scan block sums
__device__ __align__(8) int2 g_edge[N_EDGES]; // CSR payload: {col, bits(dis[col])}
__device__ int   g_is64;                    // 1 if edge_index stored as int64

// ---------------------------------------------------------------------------
// Edge-index access through an int32 view, layout-agnostic.
// ---------------------------------------------------------------------------
__device__ __forceinline__ int edge_row(const int* __restrict__ w, int e, int is64) {
    return is64 ? w[2 * e] : w[e];
}
__device__ __forceinline__ int edge_col(const int* __restrict__ w, int e, int is64) {
    return is64 ? w[2 * (N_EDGES + e)] : w[N_EDGES + e];
}

// ---------------------------------------------------------------------------
// 0) dtype detector: odd 32-bit words all zero over 1024 samples => int64.
// ---------------------------------------------------------------------------
__global__ void k_detect(const int* __restrict__ w) {
    __shared__ int nz;
    if (threadIdx.x == 0) nz = 0;
    __syncthreads();
    int bad = 0;
    #pragma unroll
    for (int i = 0; i < 4; i++) {
        int idx = 2 * (threadIdx.x + i * 256) + 1;
        if (w[idx] != 0) bad = 1;
    }
    if (bad) atomicOr(&nz, 1);
    __syncthreads();
    if (threadIdx.x == 0) g_is64 = (nz == 0) ? 1 : 0;
}

// ---------------------------------------------------------------------------
// f32x2 packed-FMA helpers (sm_100+; ptxas emits FFMA2). Compute-only asm.
// ---------------------------------------------------------------------------
__device__ __forceinline__ void fma2(unsigned long long& acc,
                                     unsigned long long a,
                                     unsigned long long b) {
    asm("fma.rn.f32x2 %0, %1, %2, %0;" : "+l"(acc) : "l"(a), "l"(b));
}
__device__ __forceinline__ unsigned long long pack2(float lo, float hi) {
    unsigned long long r;
    asm("mov.b64 %0, {%1, %2};" : "=l"(r) : "f"(lo), "f"(hi));
    return r;
}
__device__ __forceinline__ float2 unpack2(unsigned long long v) {
    float2 f;
    asm("mov.b64 {%0, %1}, %2;" : "=f"(f.x), "=f"(f.y) : "l"(v));
    return f;
}

// ---------------------------------------------------------------------------
// 1) zero degree + count buffers
// ---------------------------------------------------------------------------
__global__ void k_zero() {
    int i = blockIdx.x * blockDim.x + threadIdx.x;
    if (i < N_NODES) { g_dis[i] = 0.0f; g_cnt[i] = 0; }
}

// ---------------------------------------------------------------------------
// 2) fused weighted in-degree + edge histogram
// ---------------------------------------------------------------------------
__global__ void k_deg_accum(const int* __restrict__ ei,
                            const float* __restrict__ ew) {
    int e = blockIdx.x * blockDim.x + threadIdx.x;
    if (e < N_EDGES) {
        int is64 = g_is64;
        int r = edge_row(ei, e, is64);
        if ((unsigned)r < N_NODES) {
            atomicAdd(&g_dis[r], ew[e]);
            atomicAdd(&g_cnt[r], 1);
        }
    }
}

// ---------------------------------------------------------------------------
// 3) deg -> deg^-1/2 (0 where deg == 0)
// ---------------------------------------------------------------------------
__global__ void k_deg_inv_sqrt() {
    int i = blockIdx.x * blockDim.x + threadIdx.x;
    if (i < N_NODES) {
        float d = g_dis[i];
        g_dis[i] = (d > 0.0f) ? rsqrtf(d) : 0.0f;
    }
}

// ---------------------------------------------------------------------------
// 4a) scan step 1: per-block exclusive scan of g_cnt -> g_off, block sums
// ---------------------------------------------------------------------------
__global__ void __launch_bounds__(SCAN_BLK) k_scan1() {
    __shared__ int s[SCAN_BLK];
    int t = threadIdx.x;
    int i = blockIdx.x * SCAN_BLK + t;
    int v = (i < N_NODES) ? g_cnt[i] : 0;
    s[t] = v;
    __syncthreads();
    #pragma unroll
    for (int off = 1; off < SCAN_BLK; off <<= 1) {
        int x = (t >= off) ? s[t - off] : 0;
        __syncthreads();
        s[t] += x;
        __syncthreads();
    }
    if (i < N_NODES) g_off[i] = s[t] - v;          // exclusive
    if (t == SCAN_BLK - 1) g_bsum[blockIdx.x] = s[t];
}

// ---------------------------------------------------------------------------
// 4b) scan step 2: serial exclusive scan of 98 block sums (trivial)
// ---------------------------------------------------------------------------
__global__ void k_scan2() {
    if (threadIdx.x == 0) {
        int carry = 0;
        #pragma unroll 1
        for (int i = 0; i < N_SCAN_BLK; i++) {
            int v = g_bsum[i];
            g_bsum[i] = carry;
            carry += v;
        }
    }
}

// ---------------------------------------------------------------------------
// 4c) scan step 3: add block offsets
// ---------------------------------------------------------------------------
__global__ void __launch_bounds__(SCAN_BLK) k_scan3() {
    int i = blockIdx.x * SCAN_BLK + threadIdx.x;
    if (i < N_NODES) g_off[i] += g_bsum[blockIdx.x];
}

// ---------------------------------------------------------------------------
// 5) CSR fill: g_off used as cursor; after this, g_off[r] = end of node r.
//    Payload packs {col, dis[col]} so the gather never touches ei/dis again.
// ---------------------------------------------------------------------------
__global__ void k_fill(const int* __restrict__ ei) {
    int e = blockIdx.x * blockDim.x + threadIdx.x;
    if (e < N_EDGES) {
        int is64 = g_is64;
        int r   = edge_row(ei, e, is64);
        int col = edge_col(ei, e, is64);
        if ((unsigned)r >= N_NODES || (unsigned)col >= N_NODES) return;
        int pos = atomicAdd(&g_off[r], 1);
        g_edge[pos] = make_int2(col, __float_as_int(g_dis[col]));
    }
}

// ---------------------------------------------------------------------------
// 6) GEMM: g_h[100000,64] = x[100000,128] @ W[128,64]  (FFMA2, tiled)
// ---------------------------------------------------------------------------
#define XS_STRIDE 68

__global__ void __launch_bounds__(256) k_gemm(const float* __restrict__ x,
                                              const float* __restrict__ W) {
    __shared__ __align__(16) float Ws[IN_CH * OUT_CH];   // 32 KB
    __shared__ __align__(16) float Xs[64 * XS_STRIDE];   // 17 KB

    const int t  = threadIdx.x;
    const int tx = t & 15;
    const int ty = t >> 4;
    const int nb = blockIdx.x * 64;

    {
        const float4* W4 = reinterpret_cast<const float4*>(W);
        float4* Ws4 = reinterpret_cast<float4*>(Ws);
        #pragma unroll
        for (int i = 0; i < (IN_CH * OUT_CH / 4) / 256; i++)
            Ws4[t + i * 256] = W4[t + i * 256];
    }

    unsigned long long acc[4][2];
    #pragma unroll
    for (int i = 0; i < 4; i++) { acc[i][0] = 0ull; acc[i][1] = 0ull; }

    #pragma unroll
    for (int kc = 0; kc < 2; kc++) {
        {
            const float4* x4 = reinterpret_cast<const float4*>(x);
            #pragma unroll
            for (int i = 0; i < 4; i++) {
                int f = t + i * 256;
                int node = f >> 4;
                int kk4  = f & 15;
                int gn = nb + node;
                float4 v = make_float4(0.f, 0.f, 0.f, 0.f);
                if (gn < N_NODES)
                    v = x4[(size_t)gn * (IN_CH / 4) + kc * 16 + kk4];
                *reinterpret_cast<float4*>(&Xs[node * XS_STRIDE + kk4 * 4]) = v;
            }
        }
        __syncthreads();

        #pragma unroll 8
        for (int kk = 0; kk < 64; kk++) {
            float4 w = *reinterpret_cast<const float4*>(
                &Ws[(kc * 64 + kk) * OUT_CH + tx * 4]);
            unsigned long long wA = pack2(w.x, w.y);
            unsigned long long wB = pack2(w.z, w.w);
            #pragma unroll
            for (int i = 0; i < 4; i++) {
                float xv = Xs[(ty * 4 + i) * XS_STRIDE + kk];
                unsigned long long x2 = pack2(xv, xv);
                fma2(acc[i][0], x2, wA);
                fma2(acc[i][1], x2, wB);
            }
        }
        __syncthreads();
    }

    #pragma unroll
    for (int i = 0; i < 4; i++) {
        int node = nb + ty * 4 + i;
        if (node < N_NODES) {
            float2 a = unpack2(acc[i][0]);
            float2 b = unpack2(acc[i][1]);
            float4 v = make_float4(a.x, a.y, b.x, b.y);
            *reinterpret_cast<float4*>(&g_h[(size_t)node * OUT_CH + tx * 4]) = v;
        }
    }
}

// ---------------------------------------------------------------------------
// 7) atomic-free gather: one warp per node, lane owns 2 output channels.
//    out[r] = (sum_e h[col_e] * dis[col_e]) * dis[r] + b
// ---------------------------------------------------------------------------
__global__ void __launch_bounds__(256) k_gather(const float* __restrict__ b,
                                                float* __restrict__ out) {
    int warp = (blockIdx.x * blockDim.x + threadIdx.x) >> 5;
    int lane = threadIdx.x & 31;
    if (warp >= N_NODES) return;

    int end = g_off[warp];          // post-fill cursor = end
    int deg = g_cnt[warp];
    const int2* ep = g_edge + (end - deg);

    float2 acc = make_float2(0.0f, 0.0f);

    int i = 0;
    // 2-wide software pipeline for memory-level parallelism
    for (; i + 2 <= deg; i += 2) {
        int2 p0 = ep[i];
        int2 p1 = ep[i + 1];
        float s0 = __int_as_float(p0.y);
        float s1 = __int_as_float(p1.y);
        float2 h0 = *reinterpret_cast<const float2*>(&g_h[(size_t)p0.x * OUT_CH + lane * 2]);
        float2 h1 = *reinterpret_cast<const float2*>(&g_h[(size_t)p1.x * OUT_CH + lane * 2]);
        acc.x += h0.x * s0; acc.y += h0.y * s0;
        acc.x += h1.x * s1; acc.y += h1.y * s1;
    }
    if (i < deg) {
        int2 p0 = ep[i];
        float s0 = __int_as_float(p0.y);
        float2 h0 = *reinterpret_cast<const float2*>(&g_h[(size_t)p0.x * OUT_CH + lane * 2]);
        acc.x += h0.x * s0; acc.y += h0.y * s0;
    }

    float dr = g_dis[warp];
    float2 bv = *reinterpret_cast<const float2*>(&b[lane * 2]);
    float2 o = make_float2(acc.x * dr + bv.x, acc.y * dr + bv.y);
    *reinterpret_cast<float2*>(&out[(size_t)warp * OUT_CH + lane * 2]) = o;
}

// ---------------------------------------------------------------------------
// launch
// ---------------------------------------------------------------------------
extern "C" void kernel_launch(void* const* d_in, const int* in_sizes, int n_in,
                              void* d_out, int out_size) {
    const float* x  = (const float*)d_in[0];
    const int*   ei = (const int*)d_in[1];     // int32 view; layout detected on-device
    const float* ew = (const float*)d_in[2];
    const float* W  = (const float*)d_in[3];
    const float* b  = (const float*)d_in[4];
    float* out = (float*)d_out;

    k_detect<<<1, 256>>>(ei);
    k_zero<<<(N_NODES + 255) / 256, 256>>>();
    k_deg_accum<<<(N_EDGES + 255) / 256, 256>>>(ei, ew);
    k_deg_inv_sqrt<<<(N_NODES + 255) / 256, 256>>>();

    // CSR build
    k_scan1<<<N_SCAN_BLK, SCAN_BLK>>>();
    k_scan2<<<1, 32>>>();
    k_scan3<<<N_SCAN_BLK, SCAN_BLK>>>();
    k_fill<<<(N_EDGES + 255) / 256, 256>>>(ei);

    // dense transform
    k_gemm<<<(N_NODES + 63) / 64, 256>>>(x, W);

    // atomic-free aggregate + bias
    int gather_blocks = (N_NODES * 32 + 255) / 256;
    k_gather<<<gather_blocks, 256>>>(b, out);
}